// round 16
// baseline (speedup 1.0000x reference)
#include <cuda_runtime.h>
#include <cfloat>

// ---------------------------------------------------------------------------
// PillarMaxPooling: h = relu((x @ W) * bn_scale + bn_shift); segment_max -> M
//   k1: counting-bucket scatter of point IDS (int4-vectorized)
//   k2: warp per PILLAR PAIR, pipelined (R10 skeleton). Lanes 0-15 serve
//       pillar 2p, lanes 16-31 serve pillar 2p+1 (16-pt hot chunk each).
//       All per-iteration overhead amortized over 2 pillars; pair-packed
//       SMEM + f32x2 point-pair mainloop unchanged. Grid = one wave.
// ---------------------------------------------------------------------------

#define CAP      64
#define MAXM     262144
#define OVFCAP   65536
#define BN_EPS   1e-3f
#define K2_THREADS 256
#define K2_WARPS   8
#define K2_GRID  444
#define HCH      16             // hot-path points per pillar (half-warp)

__device__ int   d_count[MAXM];                 // zero-init, k2 re-zeroes
__device__ int   d_bucket[(size_t)MAXM * CAP];
__device__ int   d_ovflist[OVFCAP];
__device__ int   d_ovfcnt;                      // zero-init

typedef unsigned long long u64;

__device__ __forceinline__ u64 pk2(float x, float y) {
    u64 r; asm("mov.b64 %0, {%1, %2};" : "=l"(r) : "f"(x), "f"(y)); return r;
}
__device__ __forceinline__ void upk2(u64 v, float& x, float& y) {
    asm("mov.b64 {%0, %1}, %2;" : "=f"(x), "=f"(y) : "l"(v));
}
__device__ __forceinline__ u64 fma2(u64 a, u64 b, u64 c) {
    u64 d; asm("fma.rn.f32x2 %0, %1, %2, %3;" : "=l"(d) : "l"(a), "l"(b), "l"(c)); return d;
}
__device__ __forceinline__ u64 mul2(u64 a, u64 b) {
    u64 d; asm("mul.rn.f32x2 %0, %1, %2;" : "=l"(d) : "l"(a), "l"(b)); return d;
}

__device__ __forceinline__ void put_point(int i, int p) {
    int s = atomicAdd(&d_count[i], 1);
    if (s < CAP) {
        d_bucket[(unsigned)i * CAP + s] = p;
    } else {
        int o = atomicAdd(&d_ovfcnt, 1);
        if (o < OVFCAP) d_ovflist[o] = p;
        else atomicSub(&d_ovfcnt, 1);
    }
}

__global__ void k1_scatter(const int* __restrict__ idx, int P) {
    int t  = blockIdx.x * blockDim.x + threadIdx.x;
    int p0 = t * 4;
    if (p0 + 3 < P) {
        int4 v = *reinterpret_cast<const int4*>(idx + p0);
        put_point(v.x, p0);
        put_point(v.y, p0 + 1);
        put_point(v.z, p0 + 2);
        put_point(v.w, p0 + 3);
    } else {
        for (int p = p0; p < P; p++) put_point(idx[p], p);
    }
}

// Point-pair mainloop: word (pr*20 + 2k + par) = feature k of point 2pr+par.
__device__ __forceinline__ void pair_mainloop(const float* buf, int m,
                                              const u64* wA, const u64* wB,
                                              float& mA, float& mB) {
    int  pairs = (m + 1) >> 1;
    bool odd   = (m & 1) != 0;
#pragma unroll 2
    for (int pr = 0; pr < pairs; pr++) {
        const ulonglong2* q = reinterpret_cast<const ulonglong2*>(buf + pr * 20);
        ulonglong2 q0 = q[0], q1 = q[1], q2 = q[2], q3 = q[3], q4 = q[4];
        u64 a = mul2(q0.x, wA[0]);
        u64 b = mul2(q0.x, wB[0]);
        a = fma2(q0.y, wA[1], a);  b = fma2(q0.y, wB[1], b);
        a = fma2(q1.x, wA[2], a);  b = fma2(q1.x, wB[2], b);
        a = fma2(q1.y, wA[3], a);  b = fma2(q1.y, wB[3], b);
        a = fma2(q2.x, wA[4], a);  b = fma2(q2.x, wB[4], b);
        a = fma2(q2.y, wA[5], a);  b = fma2(q2.y, wB[5], b);
        a = fma2(q3.x, wA[6], a);  b = fma2(q3.x, wB[6], b);
        a = fma2(q3.y, wA[7], a);  b = fma2(q3.y, wB[7], b);
        a = fma2(q4.x, wA[8], a);  b = fma2(q4.x, wB[8], b);
        a = fma2(q4.y, wA[9], a);  b = fma2(q4.y, wB[9], b);
        float xe, xo, ye, yo;
        upk2(a, xe, xo);
        upk2(b, ye, yo);
        if (odd && pr == pairs - 1) { xo = -FLT_MAX; yo = -FLT_MAX; }
        mA = fmaxf(fmaxf(mA, xe), xo);
        mB = fmaxf(fmaxf(mB, ye), yo);
    }
}

// Rare-path helper: extra chunks (HCH < n <= CAP) + overflow, for pillar i.
__device__ __noinline__ void slow_tail(const float* __restrict__ gf,
                                       const int* __restrict__ idx,
                                       float* buf, int lane, int i, int n,
                                       const u64* wA, const u64* wB,
                                       float& mA, float& mB) {
    int nc = n < CAP ? n : CAP;
    for (int base = HCH; base < nc; base += HCH) {
        int m = nc - base; if (m > HCH) m = HCH;
        __syncwarp();
        if (lane < m) {
            int pid = d_bucket[(unsigned)i * CAP + base + lane];
            const float2* row = reinterpret_cast<const float2*>(gf + (unsigned)pid * 10u);
            float2 v0 = row[0], v1 = row[1], v2 = row[2], v3 = row[3], v4 = row[4];
            float vv[10] = {v0.x,v0.y,v1.x,v1.y,v2.x,v2.y,v3.x,v3.y,v4.x,v4.y};
            float* s = buf + (lane >> 1) * 20 + (lane & 1);
#pragma unroll
            for (int k = 0; k < 10; k++) s[2 * k] = vv[k];
        }
        __syncwarp();
        pair_mainloop(buf, m, wA, wB, mA, mB);
    }
    if (n > CAP) {
        int V = d_ovfcnt; if (V > OVFCAP) V = OVFCAP;
        int mine = 0;
        for (int e = 0; e < V; e++) {
            int pid = d_ovflist[e];
            if (idx[pid] == i) {
                mine++;
                u64 a = pk2(0.f, 0.f), b = a;
#pragma unroll
                for (int k = 0; k < 10; k++) {
                    float f = gf[(unsigned)pid * 10u + k];
                    u64 ff = pk2(f, f);
                    a = fma2(ff, wA[k], a);
                    b = fma2(ff, wB[k], b);
                }
                float xa, t0, ya, t1;
                upk2(a, xa, t0); upk2(b, ya, t1);
                mA = fmaxf(mA, xa);
                mB = fmaxf(mB, ya);
            }
        }
        if (lane == 0 && mine) atomicSub(&d_ovfcnt, mine);
    }
}

__global__ void __launch_bounds__(K2_THREADS, 3)
k2_compute(const float* __restrict__ gf, const float* __restrict__ W,
           const float* __restrict__ gamma, const float* __restrict__ beta,
           const float* __restrict__ mean,  const float* __restrict__ var,
           const int* __restrict__ idx, float* __restrict__ out, int M) {
    __shared__ __align__(16) float sm[K2_WARPS][2][320];   // 20 KB (2 halves x 160)

    int lane = threadIdx.x & 31;
    int wloc = threadIdx.x >> 5;
    int slot = lane & 15;
    int half = lane >> 4;          // 0 = pillar A (2p), 1 = pillar B (2p+1)

    int gwarp = (blockIdx.x * K2_THREADS + threadIdx.x) >> 5;
    int nw    = (gridDim.x * K2_THREADS) >> 5;
    int PQ    = (M + 1) >> 1;      // number of pillar pairs

    int cA = 2 * lane, cB = 2 * lane + 1;
    float sA = gamma[cA] * rsqrtf(var[cA] + BN_EPS);
    float sB = gamma[cB] * rsqrtf(var[cB] + BN_EPS);
    float bA = beta[cA] - mean[cA] * sA;
    float bB = beta[cB] - mean[cB] * sB;

    u64 wA[10], wB[10];
#pragma unroll
    for (int k = 0; k < 10; k++) {
        float a = W[k * 64 + cA] * sA;
        float b = W[k * 64 + cB] * sB;
        wA[k] = pk2(a, a);
        wB[k] = pk2(b, b);
    }

    // ---- pipeline prologue -------------------------------------------------
    int p0 = gwarp, p1 = p0 + nw, p2 = p1 + nw, p3 = p2 + nw;

    int nA0 = 0, nB0 = 0;
    if (p0 < PQ) {
        int2 c = *reinterpret_cast<const int2*>(d_count + 2 * p0);
        nA0 = c.x;
        nB0 = (2 * p0 + 1 < M) ? c.y : 0;
    }
    int mA0 = nA0 < HCH ? nA0 : HCH;
    int mB0 = nB0 < HCH ? nB0 : HCH;

    float r[10];
    {
        int mh = half ? mB0 : mA0;
        if (p0 < PQ && slot < mh) {
            int pid = d_bucket[(unsigned)(2 * p0 + half) * CAP + slot];
            const float2* row = reinterpret_cast<const float2*>(gf + (unsigned)pid * 10u);
            float2 v0 = row[0], v1 = row[1], v2 = row[2], v3 = row[3], v4 = row[4];
            r[0]=v0.x; r[1]=v0.y; r[2]=v1.x; r[3]=v1.y; r[4]=v2.x;
            r[5]=v2.y; r[6]=v3.x; r[7]=v3.y; r[8]=v4.x; r[9]=v4.y;
        }
    }
    int nA1 = 0, nB1 = 0;
    if (p1 < PQ) {
        int2 c = *reinterpret_cast<const int2*>(d_count + 2 * p1);
        nA1 = c.x;
        nB1 = (2 * p1 + 1 < M) ? c.y : 0;
    }
    int id1 = 0;
    {
        int mh = half ? (nB1 < HCH ? nB1 : HCH) : (nA1 < HCH ? nA1 : HCH);
        if (p1 < PQ && slot < mh) id1 = d_bucket[(unsigned)(2 * p1 + half) * CAP + slot];
    }
    int nA2 = 0, nB2 = 0;
    if (p2 < PQ) {
        int2 c = *reinterpret_cast<const int2*>(d_count + 2 * p2);
        nA2 = c.x;
        nB2 = (2 * p2 + 1 < M) ? c.y : 0;
    }

    int cur = 0;
    // ---- pipelined main loop ------------------------------------------------
    while (p0 < PQ) {
        float* buf = sm[wloc][cur];

        // (1) deposit rows(p0): lane's slot into its half's pair-packed region
        {
            int mh = half ? mB0 : mA0;
            if (slot < mh) {
                float* s = buf + half * 160 + (slot >> 1) * 20 + (slot & 1);
#pragma unroll
                for (int k = 0; k < 10; k++) s[2 * k] = r[k];
            }
        }
        // (2) gather rows(p1) using id1
        int mA1 = nA1 < HCH ? nA1 : HCH;
        int mB1 = nB1 < HCH ? nB1 : HCH;
        {
            int mh = half ? mB1 : mA1;
            if (p1 < PQ && slot < mh) {
                const float2* row = reinterpret_cast<const float2*>(gf + (unsigned)id1 * 10u);
                float2 v0 = row[0], v1 = row[1], v2 = row[2], v3 = row[3], v4 = row[4];
                r[0]=v0.x; r[1]=v0.y; r[2]=v1.x; r[3]=v1.y; r[4]=v2.x;
                r[5]=v2.y; r[6]=v3.x; r[7]=v3.y; r[8]=v4.x; r[9]=v4.y;
            }
        }
        // (3) ids(p2)
        int id2 = 0;
        {
            int mh = half ? (nB2 < HCH ? nB2 : HCH) : (nA2 < HCH ? nA2 : HCH);
            if (p2 < PQ && slot < mh) id2 = d_bucket[(unsigned)(2 * p2 + half) * CAP + slot];
        }
        // (4) counts(p3)
        int nA3 = 0, nB3 = 0;
        if (p3 < PQ) {
            int2 c = *reinterpret_cast<const int2*>(d_count + 2 * p3);
            nA3 = c.x;
            nB3 = (2 * p3 + 1 < M) ? c.y : 0;
        }

        __syncwarp();

        int iA = 2 * p0, iB = iA + 1;

        // (5) compute pillar A
        float mAa = -FLT_MAX, mAb = -FLT_MAX;
        pair_mainloop(buf, mA0, wA, wB, mAa, mAb);
        if (nA0 > HCH) slow_tail(gf, idx, buf, lane, iA, nA0, wA, wB, mAa, mAb);

        // (6) compute pillar B
        float mBa = -FLT_MAX, mBb = -FLT_MAX;
        pair_mainloop(buf + 160, mB0, wA, wB, mBa, mBb);
        if (nB0 > HCH) slow_tail(gf, idx, buf + 160, lane, iB, nB0, wA, wB, mBa, mBb);

        // (7) outputs + resets
        {
            float o0 = 0.0f, o1 = 0.0f;
            if (nA0 > 0) {
                o0 = fmaxf(mAa + bA, 0.0f);
                o1 = fmaxf(mAb + bB, 0.0f);
            }
            *reinterpret_cast<float2*>(out + (unsigned)iA * 64 + cA) = make_float2(o0, o1);
        }
        if (iB < M) {
            float o0 = 0.0f, o1 = 0.0f;
            if (nB0 > 0) {
                o0 = fmaxf(mBa + bA, 0.0f);
                o1 = fmaxf(mBb + bB, 0.0f);
            }
            *reinterpret_cast<float2*>(out + (unsigned)iB * 64 + cA) = make_float2(o0, o1);
        }
        if (lane == 0 && nA0 > 0) d_count[iA] = 0;
        if (lane == 1 && iB < M && nB0 > 0) d_count[iB] = 0;

        // (8) pipeline shift
        p0 = p1; nA0 = nA1; nB0 = nB1; mA0 = mA1; mB0 = mB1;
        p1 = p2; nA1 = nA2; nB1 = nB2; id1 = id2;
        p2 = p3; nA2 = nA3; nB2 = nB3;
        p3 += nw;
        cur ^= 1;
    }
}

extern "C" void kernel_launch(void* const* d_in, const int* in_sizes, int n_in,
                              void* d_out, int out_size) {
    const float* gf    = (const float*)d_in[0];
    const int*   idx   = (const int*)  d_in[1];
    const float* W     = (const float*)d_in[3];
    const float* gamma = (const float*)d_in[4];
    const float* beta  = (const float*)d_in[5];
    const float* mean  = (const float*)d_in[6];
    const float* var   = (const float*)d_in[7];
    float*       out   = (float*)d_out;

    int P = in_sizes[1];
    int M = out_size / 64;

    int g1 = (P / 4 + 255) / 256 + 1;
    k1_scatter<<<g1, 256>>>(idx, P);
    k2_compute<<<K2_GRID, K2_THREADS>>>(gf, W, gamma, beta, mean, var, idx, out, M);
}

// round 17
// speedup vs baseline: 1.3776x; 1.3776x over previous
#include <cuda_runtime.h>
#include <cfloat>

// ---------------------------------------------------------------------------
// PillarMaxPooling: h = relu((x @ W) * bn_scale + bn_shift); segment_max -> M
//   k1: counting-bucket scatter of point IDS (int4-vectorized)
//   k2: warp per PILLAR PAIR, pipelined. Lanes 0-15 serve pillar 2p, lanes
//       16-31 serve pillar 2p+1 (16-pt hot chunk). ALL slow paths inline
//       (no calls -> no ABI spills). B-half SMEM offset +168 floats debanks
//       the deposit. Pair-packed SMEM + f32x2 point-pair mainloop.
// ---------------------------------------------------------------------------

#define CAP      64
#define MAXM     262144
#define OVFCAP   65536
#define BN_EPS   1e-3f
#define K2_THREADS 256
#define K2_WARPS   8
#define K2_GRID  444
#define HCH      16              // hot-path points per pillar (half-warp)
#define BOFF     168             // pillar-B half offset in floats (bank-disjoint)
#define BUFT     512             // total floats per (warp,buffer); slow path uses 320

__device__ int   d_count[MAXM];                 // zero-init, k2 re-zeroes
__device__ int   d_bucket[(size_t)MAXM * CAP];
__device__ int   d_ovflist[OVFCAP];
__device__ int   d_ovfcnt;                      // zero-init

typedef unsigned long long u64;

__device__ __forceinline__ u64 pk2(float x, float y) {
    u64 r; asm("mov.b64 %0, {%1, %2};" : "=l"(r) : "f"(x), "f"(y)); return r;
}
__device__ __forceinline__ void upk2(u64 v, float& x, float& y) {
    asm("mov.b64 {%0, %1}, %2;" : "=f"(x), "=f"(y) : "l"(v));
}
__device__ __forceinline__ u64 fma2(u64 a, u64 b, u64 c) {
    u64 d; asm("fma.rn.f32x2 %0, %1, %2, %3;" : "=l"(d) : "l"(a), "l"(b), "l"(c)); return d;
}
__device__ __forceinline__ u64 mul2(u64 a, u64 b) {
    u64 d; asm("mul.rn.f32x2 %0, %1, %2;" : "=l"(d) : "l"(a), "l"(b)); return d;
}

__device__ __forceinline__ void put_point(int i, int p) {
    int s = atomicAdd(&d_count[i], 1);
    if (s < CAP) {
        d_bucket[(unsigned)i * CAP + s] = p;
    } else {
        int o = atomicAdd(&d_ovfcnt, 1);
        if (o < OVFCAP) d_ovflist[o] = p;
        else atomicSub(&d_ovfcnt, 1);
    }
}

__global__ void k1_scatter(const int* __restrict__ idx, int P) {
    int t  = blockIdx.x * blockDim.x + threadIdx.x;
    int p0 = t * 4;
    if (p0 + 3 < P) {
        int4 v = *reinterpret_cast<const int4*>(idx + p0);
        put_point(v.x, p0);
        put_point(v.y, p0 + 1);
        put_point(v.z, p0 + 2);
        put_point(v.w, p0 + 3);
    } else {
        for (int p = p0; p < P; p++) put_point(idx[p], p);
    }
}

// Point-pair mainloop: word (pr*20 + 2k + par) = feature k of point 2pr+par.
__device__ __forceinline__ void pair_mainloop(const float* buf, int m,
                                              const u64* wA, const u64* wB,
                                              float& mA, float& mB) {
    int  pairs = (m + 1) >> 1;
    bool odd   = (m & 1) != 0;
#pragma unroll 2
    for (int pr = 0; pr < pairs; pr++) {
        const ulonglong2* q = reinterpret_cast<const ulonglong2*>(buf + pr * 20);
        ulonglong2 q0 = q[0], q1 = q[1], q2 = q[2], q3 = q[3], q4 = q[4];
        u64 a = mul2(q0.x, wA[0]);
        u64 b = mul2(q0.x, wB[0]);
        a = fma2(q0.y, wA[1], a);  b = fma2(q0.y, wB[1], b);
        a = fma2(q1.x, wA[2], a);  b = fma2(q1.x, wB[2], b);
        a = fma2(q1.y, wA[3], a);  b = fma2(q1.y, wB[3], b);
        a = fma2(q2.x, wA[4], a);  b = fma2(q2.x, wB[4], b);
        a = fma2(q2.y, wA[5], a);  b = fma2(q2.y, wB[5], b);
        a = fma2(q3.x, wA[6], a);  b = fma2(q3.x, wB[6], b);
        a = fma2(q3.y, wA[7], a);  b = fma2(q3.y, wB[7], b);
        a = fma2(q4.x, wA[8], a);  b = fma2(q4.x, wB[8], b);
        a = fma2(q4.y, wA[9], a);  b = fma2(q4.y, wB[9], b);
        float xe, xo, ye, yo;
        upk2(a, xe, xo);
        upk2(b, ye, yo);
        if (odd && pr == pairs - 1) { xo = -FLT_MAX; yo = -FLT_MAX; }
        mA = fmaxf(fmaxf(mA, xe), xo);
        mB = fmaxf(fmaxf(mB, ye), yo);
    }
}

__global__ void __launch_bounds__(K2_THREADS, 3)
k2_compute(const float* __restrict__ gf, const float* __restrict__ W,
           const float* __restrict__ gamma, const float* __restrict__ beta,
           const float* __restrict__ mean,  const float* __restrict__ var,
           const int* __restrict__ idx, float* __restrict__ out, int M) {
    __shared__ __align__(16) float sm[K2_WARPS][2][BUFT];   // 32 KB

    int lane = threadIdx.x & 31;
    int wloc = threadIdx.x >> 5;
    int slot = lane & 15;
    int half = lane >> 4;          // 0 = pillar A (2p), 1 = pillar B (2p+1)
    int hoff = half ? BOFF : 0;

    int gwarp = (blockIdx.x * K2_THREADS + threadIdx.x) >> 5;
    int nw    = (gridDim.x * K2_THREADS) >> 5;
    int PQ    = (M + 1) >> 1;      // number of pillar pairs

    int cA = 2 * lane, cB = 2 * lane + 1;
    float sA = gamma[cA] * rsqrtf(var[cA] + BN_EPS);
    float sB = gamma[cB] * rsqrtf(var[cB] + BN_EPS);
    float bA = beta[cA] - mean[cA] * sA;
    float bB = beta[cB] - mean[cB] * sB;

    u64 wA[10], wB[10];
#pragma unroll
    for (int k = 0; k < 10; k++) {
        float a = W[k * 64 + cA] * sA;
        float b = W[k * 64 + cB] * sB;
        wA[k] = pk2(a, a);
        wB[k] = pk2(b, b);
    }

    // ---- pipeline prologue -------------------------------------------------
    int p0 = gwarp, p1 = p0 + nw, p2 = p1 + nw, p3 = p2 + nw;

    int nA0 = 0, nB0 = 0;
    if (p0 < PQ) {
        int2 c = *reinterpret_cast<const int2*>(d_count + 2 * p0);
        nA0 = c.x;
        nB0 = (2 * p0 + 1 < M) ? c.y : 0;
    }
    int mA0 = nA0 < HCH ? nA0 : HCH;
    int mB0 = nB0 < HCH ? nB0 : HCH;

    float r[10];
    {
        int mh = half ? mB0 : mA0;
        if (p0 < PQ && slot < mh) {
            int pid = d_bucket[(unsigned)(2 * p0 + half) * CAP + slot];
            const float2* row = reinterpret_cast<const float2*>(gf + (unsigned)pid * 10u);
            float2 v0 = row[0], v1 = row[1], v2 = row[2], v3 = row[3], v4 = row[4];
            r[0]=v0.x; r[1]=v0.y; r[2]=v1.x; r[3]=v1.y; r[4]=v2.x;
            r[5]=v2.y; r[6]=v3.x; r[7]=v3.y; r[8]=v4.x; r[9]=v4.y;
        }
    }
    int nA1 = 0, nB1 = 0;
    if (p1 < PQ) {
        int2 c = *reinterpret_cast<const int2*>(d_count + 2 * p1);
        nA1 = c.x;
        nB1 = (2 * p1 + 1 < M) ? c.y : 0;
    }
    int id1 = 0;
    {
        int mh = half ? (nB1 < HCH ? nB1 : HCH) : (nA1 < HCH ? nA1 : HCH);
        if (p1 < PQ && slot < mh) id1 = d_bucket[(unsigned)(2 * p1 + half) * CAP + slot];
    }
    int nA2 = 0, nB2 = 0;
    if (p2 < PQ) {
        int2 c = *reinterpret_cast<const int2*>(d_count + 2 * p2);
        nA2 = c.x;
        nB2 = (2 * p2 + 1 < M) ? c.y : 0;
    }

    int cur = 0;
    // ---- pipelined main loop ------------------------------------------------
    while (p0 < PQ) {
        float* buf = sm[wloc][cur];

        // (1) deposit rows(p0) into the lane's half (bank-disjoint halves)
        {
            int mh = half ? mB0 : mA0;
            if (slot < mh) {
                float* s = buf + hoff + (slot >> 1) * 20 + (slot & 1);
#pragma unroll
                for (int k = 0; k < 10; k++) s[2 * k] = r[k];
            }
        }
        // (2) gather rows(p1) using id1
        int mA1 = nA1 < HCH ? nA1 : HCH;
        int mB1 = nB1 < HCH ? nB1 : HCH;
        {
            int mh = half ? mB1 : mA1;
            if (p1 < PQ && slot < mh) {
                const float2* row = reinterpret_cast<const float2*>(gf + (unsigned)id1 * 10u);
                float2 v0 = row[0], v1 = row[1], v2 = row[2], v3 = row[3], v4 = row[4];
                r[0]=v0.x; r[1]=v0.y; r[2]=v1.x; r[3]=v1.y; r[4]=v2.x;
                r[5]=v2.y; r[6]=v3.x; r[7]=v3.y; r[8]=v4.x; r[9]=v4.y;
            }
        }
        // (3) ids(p2)
        int id2 = 0;
        {
            int mh = half ? (nB2 < HCH ? nB2 : HCH) : (nA2 < HCH ? nA2 : HCH);
            if (p2 < PQ && slot < mh) id2 = d_bucket[(unsigned)(2 * p2 + half) * CAP + slot];
        }
        // (4) counts(p3)
        int nA3 = 0, nB3 = 0;
        if (p3 < PQ) {
            int2 c = *reinterpret_cast<const int2*>(d_count + 2 * p3);
            nA3 = c.x;
            nB3 = (2 * p3 + 1 < M) ? c.y : 0;
        }

        __syncwarp();

        int iA = 2 * p0, iB = iA + 1;

        // (5) hot compute: both pillars from their halves
        float mAa = -FLT_MAX, mAb = -FLT_MAX;
        pair_mainloop(buf, mA0, wA, wB, mAa, mAb);
        float mBa = -FLT_MAX, mBb = -FLT_MAX;
        pair_mainloop(buf + BOFF, mB0, wA, wB, mBa, mBb);

        // (6) uncommon: pillars with n > HCH (inline, full-warp 32-pt chunks;
        //     clobbers buf, which is safe after both hot mainloops)
        if (nA0 > HCH || nB0 > HCH) {
#pragma unroll 1
            for (int which = 0; which < 2; which++) {
                int ni = which ? nB0 : nA0;
                int ii = which ? iB : iA;
                if (ni <= HCH) continue;
                float* ma = which ? &mBa : &mAa;
                float* mb = which ? &mBb : &mAb;
                int nc = ni < CAP ? ni : CAP;
                for (int base = HCH; base < nc; base += 32) {
                    int m = nc - base; if (m > 32) m = 32;
                    __syncwarp();
                    if (lane < m) {
                        int pid = d_bucket[(unsigned)ii * CAP + base + lane];
                        const float2* row = reinterpret_cast<const float2*>(gf + (unsigned)pid * 10u);
                        float2 v0 = row[0], v1 = row[1], v2 = row[2], v3 = row[3], v4 = row[4];
                        float vv[10] = {v0.x,v0.y,v1.x,v1.y,v2.x,v2.y,v3.x,v3.y,v4.x,v4.y};
                        float* s = buf + (lane >> 1) * 20 + (lane & 1);
#pragma unroll
                        for (int k = 0; k < 10; k++) s[2 * k] = vv[k];
                    }
                    __syncwarp();
                    pair_mainloop(buf, m, wA, wB, *ma, *mb);
                }
                if (ni > CAP) {   // statistically never
                    int V = d_ovfcnt; if (V > OVFCAP) V = OVFCAP;
                    int mine = 0;
                    for (int e = 0; e < V; e++) {
                        int pid = d_ovflist[e];
                        if (idx[pid] == ii) {
                            mine++;
                            u64 a = pk2(0.f, 0.f), b = a;
#pragma unroll
                            for (int k = 0; k < 10; k++) {
                                float f = gf[(unsigned)pid * 10u + k];
                                u64 ff = pk2(f, f);
                                a = fma2(ff, wA[k], a);
                                b = fma2(ff, wB[k], b);
                            }
                            float xa, t0, ya, t1;
                            upk2(a, xa, t0); upk2(b, ya, t1);
                            *ma = fmaxf(*ma, xa);
                            *mb = fmaxf(*mb, ya);
                        }
                    }
                    if (lane == 0 && mine) atomicSub(&d_ovfcnt, mine);
                }
            }
        }

        // (7) outputs + resets
        {
            float o0 = 0.0f, o1 = 0.0f;
            if (nA0 > 0) {
                o0 = fmaxf(mAa + bA, 0.0f);
                o1 = fmaxf(mAb + bB, 0.0f);
            }
            *reinterpret_cast<float2*>(out + (unsigned)iA * 64 + cA) = make_float2(o0, o1);
        }
        if (iB < M) {
            float o0 = 0.0f, o1 = 0.0f;
            if (nB0 > 0) {
                o0 = fmaxf(mBa + bA, 0.0f);
                o1 = fmaxf(mBb + bB, 0.0f);
            }
            *reinterpret_cast<float2*>(out + (unsigned)iB * 64 + cA) = make_float2(o0, o1);
        }
        if (lane == 0 && nA0 > 0) d_count[iA] = 0;
        if (lane == 1 && iB < M && nB0 > 0) d_count[iB] = 0;

        // (8) pipeline shift
        p0 = p1; nA0 = nA1; nB0 = nB1; mA0 = mA1; mB0 = mB1;
        p1 = p2; nA1 = nA2; nB1 = nB2; id1 = id2;
        p2 = p3; nA2 = nA3; nB2 = nB3;
        p3 += nw;
        cur ^= 1;
    }
}

extern "C" void kernel_launch(void* const* d_in, const int* in_sizes, int n_in,
                              void* d_out, int out_size) {
    const float* gf    = (const float*)d_in[0];
    const int*   idx   = (const int*)  d_in[1];
    const float* W     = (const float*)d_in[3];
    const float* gamma = (const float*)d_in[4];
    const float* beta  = (const float*)d_in[5];
    const float* mean  = (const float*)d_in[6];
    const float* var   = (const float*)d_in[7];
    float*       out   = (float*)d_out;

    int P = in_sizes[1];
    int M = out_size / 64;

    int g1 = (P / 4 + 255) / 256 + 1;
    k1_scatter<<<g1, 256>>>(idx, P);
    k2_compute<<<K2_GRID, K2_THREADS>>>(gf, W, gamma, beta, mean, var, idx, out, M);
}